// round 1
// baseline (speedup 1.0000x reference)
#include <cuda_runtime.h>
#include <cuda_bf16.h>

// ---------------------------------------------------------------------------
// MambaRefiner: B=2, C=64, T=512, CH=8, D_MODEL=512, D_IN=1024, D_ST=128,
// DT_R=32, K=3, L=2.
// Pipeline per layer:
//   xz   = u @ in_proj_w.T                      (SGEMM 1024x2048x512)
//   xcs  = silu(causal_dwconv3(xz[:, :1024]) + conv_b)
//   xdbl = xcs @ x_proj_w.T                     (SGEMM 1024x288x1024)
//   delta= softplus(xdbl[:, :32] @ dt_proj_w.T + dt_proj_b)  (SGEMM 1024x1024x32)
//   scan over T (warp per (b,d), 4 states/thread), fused with
//          g = (y + xcs*D) * silu(z)
//   u    = g @ out_proj_w.T                     (SGEMM 1024x512x1024)
// Final: out = scatter(u @ fc_w.T + fc_b)  -> (B,C,T,CH) layout
// ---------------------------------------------------------------------------

#define B_SZ   2
#define T_SZ   512
#define DMODEL 512
#define DIN    1024
#define DST    128
#define DTR    32
#define NROWS  (B_SZ * T_SZ)        // 1024

// scratch (device globals; no allocation allowed)
__device__ float g_u[NROWS * DMODEL];        // 1024x512
__device__ float g_xz[NROWS * 2 * DIN];      // 1024x2048
__device__ float g_xcs[NROWS * DIN];         // 1024x1024
__device__ float g_xdbl[NROWS * 288];        // 1024x288
__device__ float g_delta[NROWS * DIN];       // 1024x1024
__device__ float g_g[NROWS * DIN];           // 1024x1024

// ---------------------------------------------------------------------------
// Input transpose: u[b,t,c*8+ch] = z_q[b,c,t,ch]
// ---------------------------------------------------------------------------
__global__ void transpose_in(const float* __restrict__ zq, float* __restrict__ u)
{
    int idx = blockIdx.x * 256 + threadIdx.x;            // B*T*DMODEL = 524288
    if (idx >= B_SZ * T_SZ * DMODEL) return;
    int dm = idx & (DMODEL - 1);
    int t  = (idx >> 9) & (T_SZ - 1);
    int b  = idx >> 18;
    int c  = dm >> 3;
    int ch = dm & 7;
    u[idx] = zq[(((b * 64 + c) * T_SZ) + t) * 8 + ch];
}

// ---------------------------------------------------------------------------
// Causal depthwise conv (K=3) + bias + SiLU.  x lives in xz[:, 0:DIN].
// ---------------------------------------------------------------------------
__global__ void conv_silu(const float* __restrict__ xz,
                          const float* __restrict__ cw,
                          const float* __restrict__ cb,
                          float* __restrict__ xcs)
{
    int idx = blockIdx.x * 256 + threadIdx.x;            // B*T*DIN = 1048576
    if (idx >= B_SZ * T_SZ * DIN) return;
    int d = idx & (DIN - 1);
    int t = (idx >> 10) & (T_SZ - 1);
    int b = idx >> 19;
    const float* xp = xz + (size_t)(b * T_SZ) * (2 * DIN) + d;
    float w0 = cw[d * 3 + 0], w1 = cw[d * 3 + 1], w2 = cw[d * 3 + 2];
    float v = cb[d] + w2 * xp[(size_t)t * (2 * DIN)];
    if (t >= 1) v += w1 * xp[(size_t)(t - 1) * (2 * DIN)];
    if (t >= 2) v += w0 * xp[(size_t)(t - 2) * (2 * DIN)];
    float s = 1.f / (1.f + __expf(-v));
    xcs[idx] = v * s;
}

// ---------------------------------------------------------------------------
// SIMT SGEMM: C[M,N] = A[M,K] @ W[N,K]^T, 128x128x8 tiles, 8x8 per thread.
// EPI: 0 = plain store, 1 = softplus(acc + bias[n]), 2 = bias + scatter-out
// ---------------------------------------------------------------------------
#define BM 128
#define BN 128
#define BKk 8

template <int EPI>
__global__ void __launch_bounds__(256, 2) sgemm_nt(
    const float* __restrict__ A, int lda,
    const float* __restrict__ W, int ldw,
    float* __restrict__ C, int ldc,
    int M, int N, int Kd,
    const float* __restrict__ bias)
{
    __shared__ __align__(16) float As[BKk][BM];
    __shared__ __align__(16) float Ws[BKk][BN];

    int tid = threadIdx.x;
    int bm = blockIdx.y * BM;
    int bn = blockIdx.x * BN;

    int l_row  = tid >> 1;            // 0..127
    int l_col  = (tid & 1) * 4;       // 0 or 4
    const float* Aptr = A + (size_t)(bm + l_row) * lda + l_col;
    bool w_valid = (bn + l_row) < N;
    const float* Wptr = W + (size_t)(bn + l_row) * ldw + l_col;

    int tr = (tid >> 4) * 8;          // 0..120
    int tc = (tid & 15) * 8;          // 0..120

    float acc[8][8];
#pragma unroll
    for (int i = 0; i < 8; i++)
#pragma unroll
        for (int j = 0; j < 8; j++) acc[i][j] = 0.f;

    for (int kt = 0; kt < Kd; kt += BKk) {
        float4 av = *(const float4*)(Aptr + kt);
        float4 wv = w_valid ? *(const float4*)(Wptr + kt)
                            : make_float4(0.f, 0.f, 0.f, 0.f);
        __syncthreads();
        As[l_col + 0][l_row] = av.x;
        As[l_col + 1][l_row] = av.y;
        As[l_col + 2][l_row] = av.z;
        As[l_col + 3][l_row] = av.w;
        Ws[l_col + 0][l_row] = wv.x;
        Ws[l_col + 1][l_row] = wv.y;
        Ws[l_col + 2][l_row] = wv.z;
        Ws[l_col + 3][l_row] = wv.w;
        __syncthreads();
#pragma unroll
        for (int k = 0; k < BKk; k++) {
            float ar[8], br[8];
            *(float4*)(ar)     = *(const float4*)&As[k][tr];
            *(float4*)(ar + 4) = *(const float4*)&As[k][tr + 4];
            *(float4*)(br)     = *(const float4*)&Ws[k][tc];
            *(float4*)(br + 4) = *(const float4*)&Ws[k][tc + 4];
#pragma unroll
            for (int i = 0; i < 8; i++)
#pragma unroll
                for (int j = 0; j < 8; j++)
                    acc[i][j] = fmaf(ar[i], br[j], acc[i][j]);
        }
    }

#pragma unroll
    for (int i = 0; i < 8; i++) {
        int row = bm + tr + i;
#pragma unroll
        for (int j = 0; j < 8; j++) {
            int col = bn + tc + j;
            if (col < N) {
                float v = acc[i][j];
                if (EPI == 0) {
                    C[(size_t)row * ldc + col] = v;
                } else if (EPI == 1) {
                    v += bias[col];
                    // stable softplus = max(v,0) + log1p(exp(-|v|))
                    C[(size_t)row * ldc + col] =
                        fmaxf(v, 0.f) + log1pf(expf(-fabsf(v)));
                } else { // EPI == 2: bias + scatter to (B,C,T,CH)
                    v += bias[col];
                    int b = row >> 9, t = row & (T_SZ - 1);
                    int c = col >> 3, ch = col & 7;
                    C[(((size_t)(b * 64 + c) * T_SZ) + t) * 8 + ch] = v;
                }
            }
        }
    }
}

// ---------------------------------------------------------------------------
// Selective scan: one warp per (b,d); lane holds states s = lane + 32*j.
// Fuses g = (y + x*D) * silu(z).
// ---------------------------------------------------------------------------
__global__ void __launch_bounds__(256) scan_kernel(
    const float* __restrict__ delta, const float* __restrict__ xcs,
    const float* __restrict__ xdbl,  const float* __restrict__ xz,
    const float* __restrict__ A_log, const float* __restrict__ Dskip,
    float* __restrict__ g)
{
    int warp = threadIdx.x >> 5, lane = threadIdx.x & 31;
    int gw = blockIdx.x * 8 + warp;      // 0..2047
    int b = gw >> 10;
    int d = gw & (DIN - 1);

    size_t base = (size_t)b * T_SZ;
    const float* dl = delta + base * DIN + d;
    const float* xp = xcs   + base * DIN + d;
    const float* Bp = xdbl  + base * 288 + DTR + lane;          // B block
    const float* Cp = xdbl  + base * 288 + DTR + DST + lane;    // C block
    const float* zp = xz    + base * (2 * DIN) + DIN + d;
    float* gp = g + base * DIN + d;

    float Av0 = -__expf(A_log[(size_t)d * DST + lane]);
    float Av1 = -__expf(A_log[(size_t)d * DST + lane + 32]);
    float Av2 = -__expf(A_log[(size_t)d * DST + lane + 64]);
    float Av3 = -__expf(A_log[(size_t)d * DST + lane + 96]);
    float Dd = Dskip[d];

    float h0 = 0.f, h1 = 0.f, h2 = 0.f, h3 = 0.f;

    // prefetch t = 0
    float dt_n = dl[0], xt_n = xp[0], zn = zp[0];
    float B0n = Bp[0], B1n = Bp[32], B2n = Bp[64], B3n = Bp[96];
    float C0n = Cp[0], C1n = Cp[32], C2n = Cp[64], C3n = Cp[96];

    for (int t = 0; t < T_SZ; t++) {
        float dt_ = dt_n, xt = xt_n, zv = zn;
        float B0 = B0n, B1 = B1n, B2 = B2n, B3 = B3n;
        float C0 = C0n, C1 = C1n, C2 = C2n, C3 = C3n;
        if (t < T_SZ - 1) {
            size_t o = (size_t)(t + 1);
            dt_n = dl[o * DIN];
            xt_n = xp[o * DIN];
            zn   = zp[o * (2 * DIN)];
            const float* Bq = Bp + o * 288;
            const float* Cq = Cp + o * 288;
            B0n = Bq[0]; B1n = Bq[32]; B2n = Bq[64]; B3n = Bq[96];
            C0n = Cq[0]; C1n = Cq[32]; C2n = Cq[64]; C3n = Cq[96];
        }
        float dx = dt_ * xt;
        h0 = fmaf(__expf(dt_ * Av0), h0, dx * B0);
        h1 = fmaf(__expf(dt_ * Av1), h1, dx * B1);
        h2 = fmaf(__expf(dt_ * Av2), h2, dx * B2);
        h3 = fmaf(__expf(dt_ * Av3), h3, dx * B3);
        float y = h0 * C0;
        y = fmaf(h1, C1, y);
        y = fmaf(h2, C2, y);
        y = fmaf(h3, C3, y);
        y += __shfl_xor_sync(0xffffffffu, y, 16);
        y += __shfl_xor_sync(0xffffffffu, y, 8);
        y += __shfl_xor_sync(0xffffffffu, y, 4);
        y += __shfl_xor_sync(0xffffffffu, y, 2);
        y += __shfl_xor_sync(0xffffffffu, y, 1);
        if (lane == 0) {
            float yf = fmaf(xt, Dd, y);
            float s = 1.f / (1.f + __expf(-zv));
            gp[(size_t)t * DIN] = yf * zv * s;
        }
    }
}

// ---------------------------------------------------------------------------
extern "C" void kernel_launch(void* const* d_in, const int* in_sizes, int n_in,
                              void* d_out, int out_size)
{
    const float* zq   = (const float*)d_in[0];
    const float* ipw  = (const float*)d_in[1];
    const float* cw   = (const float*)d_in[2];
    const float* cb   = (const float*)d_in[3];
    const float* xpw  = (const float*)d_in[4];
    const float* dpw  = (const float*)d_in[5];
    const float* dpb  = (const float*)d_in[6];
    const float* alog = (const float*)d_in[7];
    const float* Dv   = (const float*)d_in[8];
    const float* opw  = (const float*)d_in[9];
    const float* fcw  = (const float*)d_in[10];
    const float* fcb  = (const float*)d_in[11];
    float* out = (float*)d_out;

    float *u, *xz, *xcs, *xdbl, *delta, *gb;
    cudaGetSymbolAddress((void**)&u,     g_u);
    cudaGetSymbolAddress((void**)&xz,    g_xz);
    cudaGetSymbolAddress((void**)&xcs,   g_xcs);
    cudaGetSymbolAddress((void**)&xdbl,  g_xdbl);
    cudaGetSymbolAddress((void**)&delta, g_delta);
    cudaGetSymbolAddress((void**)&gb,    g_g);

    transpose_in<<<(B_SZ * T_SZ * DMODEL) / 256, 256>>>(zq, u);

    for (int l = 0; l < 2; l++) {
        const float* ipwl  = ipw  + (size_t)l * (2 * DIN) * DMODEL;
        const float* cwl   = cw   + (size_t)l * DIN * 3;
        const float* cbl   = cb   + (size_t)l * DIN;
        const float* xpwl  = xpw  + (size_t)l * 288 * DIN;
        const float* dpwl  = dpw  + (size_t)l * DIN * DTR;
        const float* dpbl  = dpb  + (size_t)l * DIN;
        const float* alogl = alog + (size_t)l * DIN * DST;
        const float* Dl    = Dv   + (size_t)l * DIN;
        const float* opwl  = opw  + (size_t)l * DMODEL * DIN;

        // xz = u @ in_proj_w.T   (M=1024, N=2048, K=512)
        sgemm_nt<0><<<dim3(16, 8), 256>>>(u, DMODEL, ipwl, DMODEL,
                                          xz, 2 * DIN,
                                          NROWS, 2 * DIN, DMODEL, nullptr);
        // conv + silu
        conv_silu<<<(B_SZ * T_SZ * DIN) / 256, 256>>>(xz, cwl, cbl, xcs);
        // x_dbl = xcs @ x_proj_w.T   (M=1024, N=288, K=1024)
        sgemm_nt<0><<<dim3(3, 8), 256>>>(xcs, DIN, xpwl, DIN,
                                         xdbl, 288,
                                         NROWS, 288, DIN, nullptr);
        // delta = softplus(xdbl[:, :32] @ dt_proj_w.T + dt_proj_b)
        sgemm_nt<1><<<dim3(8, 8), 256>>>(xdbl, 288, dpwl, DTR,
                                         delta, DIN,
                                         NROWS, DIN, DTR, dpbl);
        // selective scan (fused gate)
        scan_kernel<<<(B_SZ * DIN) / 8, 256>>>(delta, xcs, xdbl, xz,
                                               alogl, Dl, gb);
        // u = g @ out_proj_w.T   (M=1024, N=512, K=1024)
        sgemm_nt<0><<<dim3(4, 8), 256>>>(gb, DIN, opwl, DIN,
                                         u, DMODEL,
                                         NROWS, DMODEL, DIN, nullptr);
    }

    // out = scatter(u @ fc_w.T + fc_b)
    sgemm_nt<2><<<dim3(4, 8), 256>>>(u, DMODEL, fcw, DMODEL,
                                     out, DMODEL,
                                     NROWS, DMODEL, DMODEL, fcb);
}

// round 2
// speedup vs baseline: 2.2504x; 2.2504x over previous
#include <cuda_runtime.h>
#include <cuda_bf16.h>

// ---------------------------------------------------------------------------
// MambaRefiner: B=2, C=64, T=512, CH=8, D_MODEL=512, D_IN=1024, D_ST=128,
// DT_R=32, K=3, L=2.
// ---------------------------------------------------------------------------

#define B_SZ   2
#define T_SZ   512
#define DMODEL 512
#define DIN    1024
#define DST    128
#define DTR    32
#define NROWS  (B_SZ * T_SZ)        // 1024
#define BKk    8

// scratch (device globals; no allocation allowed)
__device__ float g_u[NROWS * DMODEL];        // 1024x512
__device__ float g_xz[NROWS * 2 * DIN];      // 1024x2048
__device__ float g_xcs[NROWS * DIN];         // 1024x1024 (also reused as fc tmp)
__device__ float g_xdbl[NROWS * 288];        // 1024x288
__device__ float g_g[NROWS * DIN];           // 1024x1024

// ---------------------------------------------------------------------------
__global__ void zero_buf(float* __restrict__ p, int n)
{
    int i = (blockIdx.x * 256 + threadIdx.x) * 4;
    if (i < n) *(float4*)(p + i) = make_float4(0.f, 0.f, 0.f, 0.f);
}

// ---------------------------------------------------------------------------
// Input transpose: u[b,t,c*8+ch] = z_q[b,c,t,ch]
// ---------------------------------------------------------------------------
__global__ void transpose_in(const float* __restrict__ zq, float* __restrict__ u)
{
    int idx = blockIdx.x * 256 + threadIdx.x;
    if (idx >= B_SZ * T_SZ * DMODEL) return;
    int dm = idx & (DMODEL - 1);
    int t  = (idx >> 9) & (T_SZ - 1);
    int b  = idx >> 18;
    int c  = dm >> 3;
    int ch = dm & 7;
    u[idx] = zq[(((b * 64 + c) * T_SZ) + t) * 8 + ch];
}

// ---------------------------------------------------------------------------
// Causal depthwise conv (K=3) + bias + SiLU.  x lives in xz[:, 0:DIN].
// ---------------------------------------------------------------------------
__global__ void conv_silu(const float* __restrict__ xz,
                          const float* __restrict__ cw,
                          const float* __restrict__ cb,
                          float* __restrict__ xcs)
{
    int idx = blockIdx.x * 256 + threadIdx.x;
    if (idx >= B_SZ * T_SZ * DIN) return;
    int d = idx & (DIN - 1);
    int t = (idx >> 10) & (T_SZ - 1);
    int b = idx >> 19;
    const float* xp = xz + (size_t)(b * T_SZ) * (2 * DIN) + d;
    float w0 = cw[d * 3 + 0], w1 = cw[d * 3 + 1], w2 = cw[d * 3 + 2];
    float v = cb[d] + w2 * xp[(size_t)t * (2 * DIN)];
    if (t >= 1) v += w1 * xp[(size_t)(t - 1) * (2 * DIN)];
    if (t >= 2) v += w0 * xp[(size_t)(t - 2) * (2 * DIN)];
    float s = 1.f / (1.f + __expf(-v));
    xcs[idx] = v * s;
}

// ---------------------------------------------------------------------------
// SIMT SGEMM: C[M,N] (+)= A[M,K] @ W[N,K]^T
// BMt x 128 x 8 tiles, double-buffered smem, global prefetch.
// EPI: 0 = plain store, 2 = bias + scatter-to-(B,C,T,CH)
// SPLITK > 1: blockIdx.z selects a K-slice, result accumulated via atomicAdd
//             (C must be pre-zeroed; EPI must be 0).
// ---------------------------------------------------------------------------
template <int BMt, int EPI, int SPLITK>
__global__ void __launch_bounds__(256, 2) gemm_nt(
    const float* __restrict__ A, int lda,
    const float* __restrict__ W, int ldw,
    float* __restrict__ C, int ldc,
    int M, int N, int Kd,
    const float* __restrict__ bias)
{
    constexpr int TM = BMt / 16;   // 8 for BMt=128, 4 for BMt=64
    __shared__ __align__(16) float As[2][BKk][BMt];
    __shared__ __align__(16) float Ws[2][BKk][128];

    int tid = threadIdx.x;
    int bm = blockIdx.y * BMt;
    int bn = blockIdx.x * 128;
    int kbeg = (Kd / SPLITK) * blockIdx.z;
    int nk = (Kd / SPLITK) / BKk;

    bool aload = (tid < BMt * 2);
    int arow = tid >> 1;                 // valid when aload
    int acol = (tid & 1) * 4;
    int wrow = tid >> 1;
    int wcol = (tid & 1) * 4;

    const float* Aptr = A + (size_t)(bm + arow) * lda + acol + kbeg;
    bool w_ok = (bn + wrow) < N;
    const float* Wptr = W + (size_t)(bn + wrow) * ldw + wcol + kbeg;

    int tr = (tid >> 4) * TM;
    int tc = (tid & 15) * 8;

    float acc[TM][8];
#pragma unroll
    for (int i = 0; i < TM; i++)
#pragma unroll
        for (int j = 0; j < 8; j++) acc[i][j] = 0.f;

    // stage 0
    {
        float4 av = aload ? *(const float4*)Aptr : make_float4(0,0,0,0);
        float4 wv = w_ok  ? *(const float4*)Wptr : make_float4(0,0,0,0);
        if (aload) {
            As[0][acol + 0][arow] = av.x; As[0][acol + 1][arow] = av.y;
            As[0][acol + 2][arow] = av.z; As[0][acol + 3][arow] = av.w;
        }
        Ws[0][wcol + 0][wrow] = wv.x; Ws[0][wcol + 1][wrow] = wv.y;
        Ws[0][wcol + 2][wrow] = wv.z; Ws[0][wcol + 3][wrow] = wv.w;
    }
    __syncthreads();

    for (int kt = 0; kt < nk; kt++) {
        int cur = kt & 1, nxt = cur ^ 1;
        float4 av2, wv2;
        bool more = (kt + 1 < nk);
        if (more) {
            av2 = aload ? *(const float4*)(Aptr + (kt + 1) * BKk)
                        : make_float4(0,0,0,0);
            wv2 = w_ok  ? *(const float4*)(Wptr + (kt + 1) * BKk)
                        : make_float4(0,0,0,0);
        }
#pragma unroll
        for (int k = 0; k < BKk; k++) {
            float ar[TM], br[8];
            *(float4*)(ar) = *(const float4*)&As[cur][k][tr];
            if (TM == 8) *(float4*)(ar + 4) = *(const float4*)&As[cur][k][tr + 4];
            *(float4*)(br)     = *(const float4*)&Ws[cur][k][tc];
            *(float4*)(br + 4) = *(const float4*)&Ws[cur][k][tc + 4];
#pragma unroll
            for (int i = 0; i < TM; i++)
#pragma unroll
                for (int j = 0; j < 8; j++)
                    acc[i][j] = fmaf(ar[i], br[j], acc[i][j]);
        }
        if (more) {
            if (aload) {
                As[nxt][acol + 0][arow] = av2.x; As[nxt][acol + 1][arow] = av2.y;
                As[nxt][acol + 2][arow] = av2.z; As[nxt][acol + 3][arow] = av2.w;
            }
            Ws[nxt][wcol + 0][wrow] = wv2.x; Ws[nxt][wcol + 1][wrow] = wv2.y;
            Ws[nxt][wcol + 2][wrow] = wv2.z; Ws[nxt][wcol + 3][wrow] = wv2.w;
        }
        __syncthreads();
    }

#pragma unroll
    for (int i = 0; i < TM; i++) {
        int row = bm + tr + i;
#pragma unroll
        for (int j = 0; j < 8; j++) {
            int col = bn + tc + j;
            if (col < N) {
                float v = acc[i][j];
                if (SPLITK > 1) {
                    atomicAdd(&C[(size_t)row * ldc + col], v);
                } else if (EPI == 0) {
                    C[(size_t)row * ldc + col] = v;
                } else { // EPI == 2: bias + scatter to (B,C,T,CH)
                    v += bias[col];
                    int b = row >> 9, t = row & (T_SZ - 1);
                    int c = col >> 3, ch = col & 7;
                    C[(((size_t)(b * 64 + c) * T_SZ) + t) * 8 + ch] = v;
                }
            }
        }
    }
}

// ---------------------------------------------------------------------------
// fc epilogue: tmp + bias -> scatter to (B,C,T,CH)
// ---------------------------------------------------------------------------
__global__ void bias_scatter(const float* __restrict__ tmp,
                             const float* __restrict__ fcb,
                             float* __restrict__ out)
{
    int idx = blockIdx.x * 256 + threadIdx.x;   // 1024*512
    if (idx >= NROWS * DMODEL) return;
    int row = idx >> 9, col = idx & (DMODEL - 1);
    float v = tmp[idx] + fcb[col];
    int b = row >> 9, t = row & (T_SZ - 1);
    int c = col >> 3, ch = col & 7;
    out[(((size_t)(b * 64 + c) * T_SZ) + t) * 8 + ch] = v;
}

// ---------------------------------------------------------------------------
// Selective scan, chunked. Block = 8 warps, all on the same batch b, one d
// per warp; B/C/dt staged per 32-step chunk into smem (shared across warps).
// dt_proj + softplus fused: delta[t] = softplus(xdbl[t,:32] . dpw[d,:] + dpb[d])
// Fuses g = (y + x*D) * silu(z).
// ---------------------------------------------------------------------------
#define TCC 32
__global__ void __launch_bounds__(256) scan_kernel(
    const float* __restrict__ xdbl,  const float* __restrict__ xcs,
    const float* __restrict__ xz,
    const float* __restrict__ dpw,   const float* __restrict__ dpb,
    const float* __restrict__ A_log, const float* __restrict__ Dskip,
    float* __restrict__ g)
{
    __shared__ float Bs[TCC][128];
    __shared__ float Cs[TCC][128];
    __shared__ float dtS[TCC][33];
    __shared__ float dpwS[8][32];

    int tid = threadIdx.x, warp = tid >> 5, lane = tid & 31;
    int b = blockIdx.x >> 7;
    int d = (blockIdx.x & 127) * 8 + warp;
    size_t base = (size_t)b * T_SZ;

    dpwS[warp][lane] = dpw[d * DTR + lane];

    float Av0 = -__expf(A_log[(size_t)d * DST + lane]);
    float Av1 = -__expf(A_log[(size_t)d * DST + lane + 32]);
    float Av2 = -__expf(A_log[(size_t)d * DST + lane + 64]);
    float Av3 = -__expf(A_log[(size_t)d * DST + lane + 96]);
    float Dd = Dskip[d];
    float dpbd = dpb[d];

    float h0 = 0.f, h1 = 0.f, h2 = 0.f, h3 = 0.f;

    const float* xd = xdbl + base * 288;
    const float* xp = xcs + base * DIN + d;
    const float* zp = xz + base * (2 * DIN) + DIN + d;
    float* gp = g + base * DIN + d;

    for (int chunk = 0; chunk < T_SZ; chunk += TCC) {
        __syncthreads();   // previous chunk fully consumed
        // cooperative stage of B, C (32 x 128) and dt (32 x 32)
        for (int i = tid; i < TCC * 128; i += 256) {
            int r = i >> 7, cc = i & 127;
            const float* row = xd + (size_t)(chunk + r) * 288;
            Bs[r][cc] = row[DTR + cc];
            Cs[r][cc] = row[DTR + DST + cc];
        }
        for (int i = tid; i < TCC * 32; i += 256) {
            int r = i >> 5, cc = i & 31;
            dtS[r][cc] = xd[(size_t)(chunk + r) * 288 + cc];
        }
        __syncthreads();

        // per-lane t = chunk + lane values
        float xv = xp[(size_t)(chunk + lane) * DIN];
        float zv = zp[(size_t)(chunk + lane) * (2 * DIN)];
        float accd = dpbd;
#pragma unroll
        for (int r = 0; r < 32; r++)
            accd = fmaf(dtS[lane][r], dpwS[warp][r], accd);
        float dlt = fmaxf(accd, 0.f) + log1pf(__expf(-fabsf(accd)));

#pragma unroll 4
        for (int t = 0; t < TCC; t++) {
            float dt_ = __shfl_sync(0xffffffffu, dlt, t);
            float xt  = __shfl_sync(0xffffffffu, xv, t);
            float zt  = __shfl_sync(0xffffffffu, zv, t);
            float B0 = Bs[t][lane],      B1 = Bs[t][lane + 32];
            float B2 = Bs[t][lane + 64], B3 = Bs[t][lane + 96];
            float C0 = Cs[t][lane],      C1 = Cs[t][lane + 32];
            float C2 = Cs[t][lane + 64], C3 = Cs[t][lane + 96];
            float dx = dt_ * xt;
            h0 = fmaf(__expf(dt_ * Av0), h0, dx * B0);
            h1 = fmaf(__expf(dt_ * Av1), h1, dx * B1);
            h2 = fmaf(__expf(dt_ * Av2), h2, dx * B2);
            h3 = fmaf(__expf(dt_ * Av3), h3, dx * B3);
            float y = h0 * C0;
            y = fmaf(h1, C1, y);
            y = fmaf(h2, C2, y);
            y = fmaf(h3, C3, y);
            y += __shfl_xor_sync(0xffffffffu, y, 16);
            y += __shfl_xor_sync(0xffffffffu, y, 8);
            y += __shfl_xor_sync(0xffffffffu, y, 4);
            y += __shfl_xor_sync(0xffffffffu, y, 2);
            y += __shfl_xor_sync(0xffffffffu, y, 1);
            if (lane == 0) {
                float yf = fmaf(xt, Dd, y);
                float s = 1.f / (1.f + __expf(-zt));
                gp[(size_t)(chunk + t) * DIN] = yf * zt * s;
            }
        }
    }
}

// ---------------------------------------------------------------------------
extern "C" void kernel_launch(void* const* d_in, const int* in_sizes, int n_in,
                              void* d_out, int out_size)
{
    const float* zq   = (const float*)d_in[0];
    const float* ipw  = (const float*)d_in[1];
    const float* cw   = (const float*)d_in[2];
    const float* cb   = (const float*)d_in[3];
    const float* xpw  = (const float*)d_in[4];
    const float* dpw  = (const float*)d_in[5];
    const float* dpb  = (const float*)d_in[6];
    const float* alog = (const float*)d_in[7];
    const float* Dv   = (const float*)d_in[8];
    const float* opw  = (const float*)d_in[9];
    const float* fcw  = (const float*)d_in[10];
    const float* fcb  = (const float*)d_in[11];
    float* out = (float*)d_out;

    float *u, *xz, *xcs, *xdbl, *gb;
    cudaGetSymbolAddress((void**)&u,    g_u);
    cudaGetSymbolAddress((void**)&xz,   g_xz);
    cudaGetSymbolAddress((void**)&xcs,  g_xcs);
    cudaGetSymbolAddress((void**)&xdbl, g_xdbl);
    cudaGetSymbolAddress((void**)&gb,   g_g);

    transpose_in<<<(B_SZ * T_SZ * DMODEL) / 256, 256>>>(zq, u);

    for (int l = 0; l < 2; l++) {
        const float* ipwl  = ipw  + (size_t)l * (2 * DIN) * DMODEL;
        const float* cwl   = cw   + (size_t)l * DIN * 3;
        const float* cbl   = cb   + (size_t)l * DIN;
        const float* xpwl  = xpw  + (size_t)l * 288 * DIN;
        const float* dpwl  = dpw  + (size_t)l * DIN * DTR;
        const float* dpbl  = dpb  + (size_t)l * DIN;
        const float* alogl = alog + (size_t)l * DIN * DST;
        const float* Dl    = Dv   + (size_t)l * DIN;
        const float* opwl  = opw  + (size_t)l * DMODEL * DIN;

        // xz = u @ in_proj_w.T   (M=1024, N=2048, K=512): 128 blocks
        gemm_nt<128, 0, 1><<<dim3(16, 8), 256>>>(u, DMODEL, ipwl, DMODEL,
                                                 xz, 2 * DIN,
                                                 NROWS, 2 * DIN, DMODEL, nullptr);
        // u free now — zero it for this layer's out_proj accumulation
        zero_buf<<<(NROWS * DMODEL) / 1024, 256>>>(u, NROWS * DMODEL);
        // conv + silu
        conv_silu<<<(B_SZ * T_SZ * DIN) / 256, 256>>>(xz, cwl, cbl, xcs);
        // x_dbl = xcs @ x_proj_w.T  (M=1024, N=288, K=1024): split-K2, 96 blks
        zero_buf<<<(NROWS * 288) / 1024, 256>>>(xdbl, NROWS * 288);
        gemm_nt<64, 0, 2><<<dim3(3, 16, 2), 256>>>(xcs, DIN, xpwl, DIN,
                                                   xdbl, 288,
                                                   NROWS, 288, DIN, nullptr);
        // fused dt_proj + softplus + selective scan + gate
        scan_kernel<<<B_SZ * 128, 256>>>(xdbl, xcs, xz, dpwl, dpbl,
                                         alogl, Dl, gb);
        // u += g @ out_proj_w.T  (M=1024, N=512, K=1024): split-K2, 128 blks
        gemm_nt<64, 0, 2><<<dim3(4, 16, 2), 256>>>(gb, DIN, opwl, DIN,
                                                   u, DMODEL,
                                                   NROWS, DMODEL, DIN, nullptr);
    }

    // fc: tmp = u @ fc_w.T (split-K2, 128 blocks), then bias + scatter
    zero_buf<<<(NROWS * DMODEL) / 1024, 256>>>(xcs, NROWS * DMODEL);
    gemm_nt<64, 0, 2><<<dim3(4, 16, 2), 256>>>(u, DMODEL, fcw, DMODEL,
                                               xcs, DMODEL,
                                               NROWS, DMODEL, DMODEL, nullptr);
    bias_scatter<<<(NROWS * DMODEL) / 256, 256>>>(xcs, fcb, out);
}

// round 7
// speedup vs baseline: 3.3697x; 1.4974x over previous
#include <cuda_runtime.h>
#include <cuda_bf16.h>
#include <cstdint>

// ---------------------------------------------------------------------------
// MambaRefiner: B=2, C=64, T=512, CH=8, D_MODEL=512, D_IN=1024, D_ST=128,
// DT_R=32, K=3, L=2.
// GEMMs on warp-level mma.sync (bf16 split-compensated, fp32 accum) — the
// harness emits PTX for plain sm_103 (no 'a'), so tcgen05 is unavailable;
// mma.sync/ldmatrix compile for compute_103 and still use the tensor pipe.
// ---------------------------------------------------------------------------

#define B_SZ   2
#define T_SZ   512
#define DMODEL 512
#define DIN    1024
#define DST    128
#define DTR    32
#define NROWS  (B_SZ * T_SZ)        // 1024
#define SROW   72                   // padded smem row stride in bf16 (144 B)

// scratch (device globals; no allocation allowed)
__device__ float g_u[NROWS * DMODEL];
__device__ float g_xz[NROWS * 2 * DIN];
__device__ float g_xcs[NROWS * DIN];
__device__ float g_xdbl[NROWS * 288];
__device__ float g_g[NROWS * DIN];
__device__ __nv_bfloat16 g_abig[NROWS * 3 * DIN];     // up to 1024 x 3072
__device__ __nv_bfloat16 g_wbig[2048 * 3 * DMODEL];   // up to 3.15M elems

// ---------------------------------------------------------------------------
__device__ __forceinline__ uint32_t smem_u32(const void* p) {
    uint32_t a;
    asm("{ .reg .u64 t; cvta.to.shared.u64 t, %1; cvt.u32.u64 %0, t; }"
        : "=r"(a) : "l"(p));
    return a;
}
__device__ __forceinline__ void ldm_x4(uint32_t* r, uint32_t addr) {
    asm volatile("ldmatrix.sync.aligned.m8n8.x4.shared.b16 {%0,%1,%2,%3}, [%4];"
                 : "=r"(r[0]), "=r"(r[1]), "=r"(r[2]), "=r"(r[3]) : "r"(addr));
}
__device__ __forceinline__ void mma16816(float* d, const uint32_t* a,
                                         uint32_t b0, uint32_t b1) {
    asm volatile(
        "mma.sync.aligned.m16n8k16.row.col.f32.bf16.bf16.f32 "
        "{%0,%1,%2,%3}, {%4,%5,%6,%7}, {%8,%9}, {%0,%1,%2,%3};"
        : "+f"(d[0]), "+f"(d[1]), "+f"(d[2]), "+f"(d[3])
        : "r"(a[0]), "r"(a[1]), "r"(a[2]), "r"(a[3]), "r"(b0), "r"(b1));
}

// ---------------------------------------------------------------------------
__global__ void zero_buf(float* __restrict__ p, int n)
{
    int i = (blockIdx.x * 256 + threadIdx.x) * 4;
    if (i < n) *(float4*)(p + i) = make_float4(0.f, 0.f, 0.f, 0.f);
}

// ---------------------------------------------------------------------------
// split fp32 -> compensated bf16 triple along K.
// Activations (isW=0): [hi | lo | hi].  Weights (isW=1): [hi | hi | lo].
// ---------------------------------------------------------------------------
__global__ void split_bf16(const float* __restrict__ X,
                           __nv_bfloat16* __restrict__ O,
                           int total, int K, int isW)
{
    int idx = blockIdx.x * 256 + threadIdx.x;
    if (idx >= total) return;
    int r = idx / K;
    int k = idx - r * K;
    float v = X[idx];
    __nv_bfloat16 h = __float2bfloat16_rn(v);
    __nv_bfloat16 l = __float2bfloat16_rn(v - __bfloat162float(h));
    __nv_bfloat16* row = O + (size_t)r * 3 * K;
    row[k] = h;
    row[K + k]     = isW ? h : l;
    row[2 * K + k] = isW ? l : h;
}

// ---------------------------------------------------------------------------
// Warp-MMA GEMM: C[M,N] (+)= A[M,K'] @ W[N,K']^T  (K' = 3K compensated)
// 128x128 CTA tile; 8 warps (4 x 2), warp tile 32x64; bf16 m16n8k16 MMA.
// ATOMIC=true: atomicAdd epilogue (split-K; C pre-zeroed).
// ---------------------------------------------------------------------------
template <bool ATOMIC>
__global__ void __launch_bounds__(256) mma_gemm(
    const __nv_bfloat16* __restrict__ A, int lda,
    const __nv_bfloat16* __restrict__ W, int ldw,
    float* __restrict__ C, int ldc, int N, int kchunks)
{
    __shared__ __align__(16) __nv_bfloat16 sA[128 * SROW];
    __shared__ __align__(16) __nv_bfloat16 sB[128 * SROW];

    int tid = threadIdx.x, wid = tid >> 5, lane = tid & 31;
    int bm = blockIdx.y * 128, bn = blockIdx.x * 128;
    int kbeg = blockIdx.z * kchunks * 64;
    int wm = wid & 3, wn = wid >> 2;

    const __nv_bfloat16* Abase = A + (size_t)bm * lda + kbeg;
    const __nv_bfloat16* Wbase = W + (size_t)bn * ldw + kbeg;

    // loader: thread handles 4 segments; idx = tid + i*256, r=idx>>3, s=idx&7
    int lr[4], ls[4];
#pragma unroll
    for (int i = 0; i < 4; i++) {
        int idx = tid + i * 256;
        lr[i] = idx >> 3;
        ls[i] = idx & 7;
    }

    float acc[2][8][4];
#pragma unroll
    for (int mt = 0; mt < 2; mt++)
#pragma unroll
        for (int nt = 0; nt < 8; nt++)
#pragma unroll
            for (int q = 0; q < 4; q++) acc[mt][nt][q] = 0.f;

    uint32_t sA32 = smem_u32(sA), sB32 = smem_u32(sB);
    // ldmatrix lane addressing: row' = lane&15, k half = lane>>4
    int lrow = lane & 15, lkh = (lane >> 4) * 8;

    uint4 pa[4], pb[4];
#pragma unroll
    for (int i = 0; i < 4; i++) {
        pa[i] = *(const uint4*)(Abase + (size_t)lr[i] * lda + ls[i] * 8);
        pb[i] = (bn + lr[i] < N)
                ? *(const uint4*)(Wbase + (size_t)lr[i] * ldw + ls[i] * 8)
                : make_uint4(0u, 0u, 0u, 0u);
    }

    for (int kt = 0; kt < kchunks; kt++) {
#pragma unroll
        for (int i = 0; i < 4; i++) {
            *(uint4*)(sA + lr[i] * SROW + ls[i] * 8) = pa[i];
            *(uint4*)(sB + lr[i] * SROW + ls[i] * 8) = pb[i];
        }
        __syncthreads();
        if (kt + 1 < kchunks) {
            const __nv_bfloat16* Ak = Abase + (kt + 1) * 64;
            const __nv_bfloat16* Wk = Wbase + (kt + 1) * 64;
#pragma unroll
            for (int i = 0; i < 4; i++) {
                pa[i] = *(const uint4*)(Ak + (size_t)lr[i] * lda + ls[i] * 8);
                pb[i] = (bn + lr[i] < N)
                        ? *(const uint4*)(Wk + (size_t)lr[i] * ldw + ls[i] * 8)
                        : make_uint4(0u, 0u, 0u, 0u);
            }
        }
#pragma unroll
        for (int ks = 0; ks < 4; ks++) {
            uint32_t afr[2][4];
#pragma unroll
            for (int mt = 0; mt < 2; mt++) {
                uint32_t addr = sA32 +
                    2 * ((wm * 32 + mt * 16 + lrow) * SROW + ks * 16 + lkh);
                ldm_x4(afr[mt], addr);
            }
#pragma unroll
            for (int ng = 0; ng < 4; ng++) {
                uint32_t bfr[4];
                uint32_t addr = sB32 +
                    2 * ((wn * 64 + ng * 16 + lrow) * SROW + ks * 16 + lkh);
                ldm_x4(bfr, addr);
#pragma unroll
                for (int mt = 0; mt < 2; mt++) {
                    mma16816(acc[mt][ng * 2 + 0], afr[mt], bfr[0], bfr[2]);
                    mma16816(acc[mt][ng * 2 + 1], afr[mt], bfr[1], bfr[3]);
                }
            }
        }
        __syncthreads();
    }

    // epilogue: D frag: d0,d1 -> (row, col..col+1), d2,d3 -> (row+8, ...)
    int qr = lane >> 2, qc = (lane & 3) * 2;
#pragma unroll
    for (int mt = 0; mt < 2; mt++) {
#pragma unroll
        for (int nt = 0; nt < 8; nt++) {
            int row = bm + wm * 32 + mt * 16 + qr;
            int col = bn + wn * 64 + nt * 8 + qc;
            float* d = acc[mt][nt];
            if (col < N) {
                if (ATOMIC) {
                    atomicAdd(&C[(size_t)row * ldc + col],       d[0]);
                    atomicAdd(&C[(size_t)row * ldc + col + 1],   d[1]);
                    atomicAdd(&C[(size_t)(row + 8) * ldc + col],     d[2]);
                    atomicAdd(&C[(size_t)(row + 8) * ldc + col + 1], d[3]);
                } else {
                    *(float2*)&C[(size_t)row * ldc + col] =
                        make_float2(d[0], d[1]);
                    *(float2*)&C[(size_t)(row + 8) * ldc + col] =
                        make_float2(d[2], d[3]);
                }
            }
        }
    }
}

// ---------------------------------------------------------------------------
// Input transpose: u[b,t,c*8+ch] = z_q[b,c,t,ch]
// ---------------------------------------------------------------------------
__global__ void transpose_in(const float* __restrict__ zq, float* __restrict__ u)
{
    int idx = blockIdx.x * 256 + threadIdx.x;
    if (idx >= B_SZ * T_SZ * DMODEL) return;
    int dm = idx & (DMODEL - 1);
    int t  = (idx >> 9) & (T_SZ - 1);
    int b  = idx >> 18;
    int c  = dm >> 3;
    int ch = dm & 7;
    u[idx] = zq[(((b * 64 + c) * T_SZ) + t) * 8 + ch];
}

// ---------------------------------------------------------------------------
// Causal depthwise conv (K=3) + bias + SiLU.  x lives in xz[:, 0:DIN].
// ---------------------------------------------------------------------------
__global__ void conv_silu(const float* __restrict__ xz,
                          const float* __restrict__ cw,
                          const float* __restrict__ cb,
                          float* __restrict__ xcs)
{
    int idx = blockIdx.x * 256 + threadIdx.x;
    if (idx >= B_SZ * T_SZ * DIN) return;
    int d = idx & (DIN - 1);
    int t = (idx >> 10) & (T_SZ - 1);
    int b = idx >> 19;
    const float* xp = xz + (size_t)(b * T_SZ) * (2 * DIN) + d;
    float w0 = cw[d * 3 + 0], w1 = cw[d * 3 + 1], w2 = cw[d * 3 + 2];
    float v = cb[d] + w2 * xp[(size_t)t * (2 * DIN)];
    if (t >= 1) v += w1 * xp[(size_t)(t - 1) * (2 * DIN)];
    if (t >= 2) v += w0 * xp[(size_t)(t - 2) * (2 * DIN)];
    float s = 1.f / (1.f + __expf(-v));
    xcs[idx] = v * s;
}

// ---------------------------------------------------------------------------
// fc epilogue: tmp + bias -> scatter to (B,C,T,CH)
// ---------------------------------------------------------------------------
__global__ void bias_scatter(const float* __restrict__ tmp,
                             const float* __restrict__ fcb,
                             float* __restrict__ out)
{
    int idx = blockIdx.x * 256 + threadIdx.x;
    if (idx >= NROWS * DMODEL) return;
    int row = idx >> 9, col = idx & (DMODEL - 1);
    float v = tmp[idx] + fcb[col];
    int b = row >> 9, t = row & (T_SZ - 1);
    int c = col >> 3, ch = col & 7;
    out[(((size_t)(b * 64 + c) * T_SZ) + t) * 8 + ch] = v;
}

// ---------------------------------------------------------------------------
// Selective scan (chunked, smem-staged), fused dt_proj+softplus and gate.
// ---------------------------------------------------------------------------
#define TCC 32
__global__ void __launch_bounds__(256) scan_kernel(
    const float* __restrict__ xdbl,  const float* __restrict__ xcs,
    const float* __restrict__ xz,
    const float* __restrict__ dpw,   const float* __restrict__ dpb,
    const float* __restrict__ A_log, const float* __restrict__ Dskip,
    float* __restrict__ g)
{
    __shared__ float Bs[TCC][128];
    __shared__ float Cs[TCC][128];
    __shared__ float dtS[TCC][33];
    __shared__ float dpwS[8][32];

    int tid = threadIdx.x, warp = tid >> 5, lane = tid & 31;
    int b = blockIdx.x >> 7;
    int d = (blockIdx.x & 127) * 8 + warp;
    size_t base = (size_t)b * T_SZ;

    dpwS[warp][lane] = dpw[d * DTR + lane];

    float Av0 = -__expf(A_log[(size_t)d * DST + lane]);
    float Av1 = -__expf(A_log[(size_t)d * DST + lane + 32]);
    float Av2 = -__expf(A_log[(size_t)d * DST + lane + 64]);
    float Av3 = -__expf(A_log[(size_t)d * DST + lane + 96]);
    float Dd = Dskip[d];
    float dpbd = dpb[d];

    float h0 = 0.f, h1 = 0.f, h2 = 0.f, h3 = 0.f;

    const float* xd = xdbl + base * 288;
    const float* xp = xcs + base * DIN + d;
    const float* zp = xz + base * (2 * DIN) + DIN + d;
    float* gp = g + base * DIN + d;

    for (int chunk = 0; chunk < T_SZ; chunk += TCC) {
        __syncthreads();
        for (int i = tid; i < TCC * 128; i += 256) {
            int r = i >> 7, cc = i & 127;
            const float* row = xd + (size_t)(chunk + r) * 288;
            Bs[r][cc] = row[DTR + cc];
            Cs[r][cc] = row[DTR + DST + cc];
        }
        for (int i = tid; i < TCC * 32; i += 256) {
            int r = i >> 5, cc = i & 31;
            dtS[r][cc] = xd[(size_t)(chunk + r) * 288 + cc];
        }
        __syncthreads();

        float xv = xp[(size_t)(chunk + lane) * DIN];
        float zv = zp[(size_t)(chunk + lane) * (2 * DIN)];
        float accd = dpbd;
#pragma unroll
        for (int r = 0; r < 32; r++)
            accd = fmaf(dtS[lane][r], dpwS[warp][r], accd);
        float dlt = fmaxf(accd, 0.f) + log1pf(__expf(-fabsf(accd)));

#pragma unroll 4
        for (int t = 0; t < TCC; t++) {
            float dt_ = __shfl_sync(0xffffffffu, dlt, t);
            float xt  = __shfl_sync(0xffffffffu, xv, t);
            float zt  = __shfl_sync(0xffffffffu, zv, t);
            float B0 = Bs[t][lane],      B1 = Bs[t][lane + 32];
            float B2 = Bs[t][lane + 64], B3 = Bs[t][lane + 96];
            float C0 = Cs[t][lane],      C1 = Cs[t][lane + 32];
            float C2 = Cs[t][lane + 64], C3 = Cs[t][lane + 96];
            float dx = dt_ * xt;
            h0 = fmaf(__expf(dt_ * Av0), h0, dx * B0);
            h1 = fmaf(__expf(dt_ * Av1), h1, dx * B1);
            h2 = fmaf(__expf(dt_ * Av2), h2, dx * B2);
            h3 = fmaf(__expf(dt_ * Av3), h3, dx * B3);
            float y = h0 * C0;
            y = fmaf(h1, C1, y);
            y = fmaf(h2, C2, y);
            y = fmaf(h3, C3, y);
            y += __shfl_xor_sync(0xffffffffu, y, 16);
            y += __shfl_xor_sync(0xffffffffu, y, 8);
            y += __shfl_xor_sync(0xffffffffu, y, 4);
            y += __shfl_xor_sync(0xffffffffu, y, 2);
            y += __shfl_xor_sync(0xffffffffu, y, 1);
            if (lane == 0) {
                float yf = fmaf(xt, Dd, y);
                float s = 1.f / (1.f + __expf(-zt));
                gp[(size_t)(chunk + t) * DIN] = yf * zt * s;
            }
        }
    }
}

// ---------------------------------------------------------------------------
extern "C" void kernel_launch(void* const* d_in, const int* in_sizes, int n_in,
                              void* d_out, int out_size)
{
    const float* zq   = (const float*)d_in[0];
    const float* ipw  = (const float*)d_in[1];
    const float* cw   = (const float*)d_in[2];
    const float* cb   = (const float*)d_in[3];
    const float* xpw  = (const float*)d_in[4];
    const float* dpw  = (const float*)d_in[5];
    const float* dpb  = (const float*)d_in[6];
    const float* alog = (const float*)d_in[7];
    const float* Dv   = (const float*)d_in[8];
    const float* opw  = (const float*)d_in[9];
    const float* fcw  = (const float*)d_in[10];
    const float* fcb  = (const float*)d_in[11];
    float* out = (float*)d_out;

    float *u, *xz, *xcs, *xdbl, *gb;
    __nv_bfloat16 *ab, *wb;
    cudaGetSymbolAddress((void**)&u,    g_u);
    cudaGetSymbolAddress((void**)&xz,   g_xz);
    cudaGetSymbolAddress((void**)&xcs,  g_xcs);
    cudaGetSymbolAddress((void**)&xdbl, g_xdbl);
    cudaGetSymbolAddress((void**)&gb,   g_g);
    cudaGetSymbolAddress((void**)&ab,   g_abig);
    cudaGetSymbolAddress((void**)&wb,   g_wbig);

    transpose_in<<<(B_SZ * T_SZ * DMODEL) / 256, 256>>>(zq, u);

    for (int l = 0; l < 2; l++) {
        const float* ipwl  = ipw  + (size_t)l * (2 * DIN) * DMODEL;
        const float* cwl   = cw   + (size_t)l * DIN * 3;
        const float* cbl   = cb   + (size_t)l * DIN;
        const float* xpwl  = xpw  + (size_t)l * 288 * DIN;
        const float* dpwl  = dpw  + (size_t)l * DIN * DTR;
        const float* dpbl  = dpb  + (size_t)l * DIN;
        const float* alogl = alog + (size_t)l * DIN * DST;
        const float* Dl    = Dv   + (size_t)l * DIN;
        const float* opwl  = opw  + (size_t)l * DMODEL * DIN;

        // xz = u @ in_proj_w.T   (M=1024, N=2048, K=512 -> K'=1536)
        split_bf16<<<(NROWS * DMODEL + 255) / 256, 256>>>(u, ab, NROWS * DMODEL, DMODEL, 0);
        split_bf16<<<(2048 * DMODEL + 255) / 256, 256>>>(ipwl, wb, 2048 * DMODEL, DMODEL, 1);
        mma_gemm<false><<<dim3(16, 8, 1), 256>>>(ab, 1536, wb, 1536,
                                                 xz, 2 * DIN, 2 * DIN, 24);
        // u free now — zero it for this layer's out_proj accumulation
        zero_buf<<<(NROWS * DMODEL) / 1024, 256>>>(u, NROWS * DMODEL);
        // conv + silu
        conv_silu<<<(B_SZ * T_SZ * DIN) / 256, 256>>>(xz, cwl, cbl, xcs);
        // x_dbl = xcs @ x_proj_w.T  (M=1024, N=288, K=1024 -> K'=3072, splitK4)
        split_bf16<<<(NROWS * DIN + 255) / 256, 256>>>(xcs, ab, NROWS * DIN, DIN, 0);
        split_bf16<<<(288 * DIN + 255) / 256, 256>>>(xpwl, wb, 288 * DIN, DIN, 1);
        zero_buf<<<(NROWS * 288) / 1024, 256>>>(xdbl, NROWS * 288);
        mma_gemm<true><<<dim3(3, 8, 4), 256>>>(ab, 3072, wb, 3072,
                                               xdbl, 288, 288, 12);
        // fused dt_proj + softplus + selective scan + gate
        scan_kernel<<<B_SZ * 128, 256>>>(xdbl, xcs, xz, dpwl, dpbl,
                                         alogl, Dl, gb);
        // u += g @ out_proj_w.T  (M=1024, N=512, K=1024 -> K'=3072, splitK4)
        split_bf16<<<(NROWS * DIN + 255) / 256, 256>>>(gb, ab, NROWS * DIN, DIN, 0);
        split_bf16<<<(DMODEL * DIN + 255) / 256, 256>>>(opwl, wb, DMODEL * DIN, DIN, 1);
        mma_gemm<true><<<dim3(4, 8, 4), 256>>>(ab, 3072, wb, 3072,
                                               u, DMODEL, DMODEL, 12);
    }

    // fc (M=1024, N=512, K=512 -> K'=1536, splitK2), then bias + scatter
    split_bf16<<<(NROWS * DMODEL + 255) / 256, 256>>>(u, ab, NROWS * DMODEL, DMODEL, 0);
    split_bf16<<<(DMODEL * DMODEL + 255) / 256, 256>>>(fcw, wb, DMODEL * DMODEL, DMODEL, 1);
    zero_buf<<<(NROWS * DMODEL) / 1024, 256>>>(xcs, NROWS * DMODEL);
    mma_gemm<true><<<dim3(4, 8, 2), 256>>>(ab, 1536, wb, 1536,
                                           xcs, DMODEL, DMODEL, 12);
    bias_scatter<<<(NROWS * DMODEL) / 256, 256>>>(xcs, fcb, out);
}